// round 15
// baseline (speedup 1.0000x reference)
#include <cuda_runtime.h>
#include <cuda_fp16.h>
#include <math.h>
#include <stdint.h>

// Problem constants: b=2, n=2048, d=256, e=16, h=8, dh=64, inner=512, nn=64
#define NROWS 4096

// ---- scratch (static device globals; no runtime allocation) ----
static __device__ float  g_qkv[NROWS * 1536];   // q|k|v per row (fp32); reused as split-K partials
static __device__ __half g_kvh[NROWS * 1024];   // k|v per row (fp16) for gathers
static __device__ float  g_att[NROWS * 512];    // attention feature output
static __device__ int    g_nb[NROWS * 64];      // neighbor indices

__device__ __forceinline__ float gelu_exact(float x){
    return 0.5f * x * (1.0f + erff(x * 0.7071067811865475f));
}

__device__ __forceinline__ float fast_tanh(float x){
    float r;
    asm("tanh.approx.f32 %0, %1;" : "=f"(r) : "f"(x));
    return r;
}

// FMA-pipe sincos: quadrant reduction + minimax polys (no MUFU).
__device__ __forceinline__ void fast_sincos(float ang, float* sv, float* cv){
    float nq = rintf(ang * 0.63661977236758134f);   // 2/pi
    int qi = (int)nq;
    float r = fmaf(nq, -1.5707963705062866f, ang);
    r = fmaf(nq, 4.3711390001862428e-8f, r);
    float r2 = r * r;
    float sp = fmaf(fmaf(fmaf(-1.9515296e-4f, r2, 8.3321638e-3f), r2,
                         -1.6666654e-1f), r2, 1.f) * r;
    float cp = fmaf(fmaf(fmaf(-1.3853704e-3f, r2, 4.1663683e-2f), r2,
                         -4.9999905e-1f), r2, 1.f);
    float s_ = (qi & 1) ? cp : sp;
    float c_ = (qi & 1) ? sp : cp;
    if (qi & 2) s_ = -s_;
    if ((qi + 1) & 2) c_ = -c_;
    *sv = s_; *cv = c_;
}

__device__ __forceinline__ float f2tf32(float x){
    uint32_t u;
    asm("cvt.rna.tf32.f32 %0, %1;" : "=r"(u) : "f"(x));
    return __uint_as_float(u);
}

__device__ __forceinline__ void mma_tf32(float c[4], uint32_t a0, uint32_t a1,
                                         uint32_t a2, uint32_t a3,
                                         uint32_t b0, uint32_t b1){
    asm volatile(
        "mma.sync.aligned.m16n8k8.row.col.f32.tf32.tf32.f32 "
        "{%0,%1,%2,%3}, {%4,%5,%6,%7}, {%8,%9}, {%0,%1,%2,%3};"
        : "+f"(c[0]), "+f"(c[1]), "+f"(c[2]), "+f"(c[3])
        : "r"(a0), "r"(a1), "r"(a2), "r"(a3), "r"(b0), "r"(b1));
}

// ============================================================
// QKV GEMM: 128x64 tile tf32 MMA, (4096,256)@(256,1536);
// epilogue packs fp16 k|v (cols >= 512).
// ============================================================
__global__ void __launch_bounds__(256) qkv_tc_kernel(
    const float* __restrict__ A, const float* __restrict__ B,
    float* __restrict__ C, __half* __restrict__ KVH)
{
    const int K = 256, N = 1536;
    __shared__ float As[2][16][136];
    __shared__ float Bs[2][16][72];

    int t = threadIdx.x;
    int warp = t >> 5, lane = t & 31;
    int wm = warp & 1, wn = warp >> 1;
    int g = lane >> 2, tg = lane & 3;
    int bx = blockIdx.x;
    int m0 = (bx / 24) * 128, n0 = (bx % 24) * 64;
    const float* Ab = A + (size_t)m0 * K;
    const float* Bb = B + n0;

    float acc[4][2][4];
#pragma unroll
    for (int ma = 0; ma < 4; ma++)
#pragma unroll
        for (int na = 0; na < 2; na++)
#pragma unroll
            for (int q = 0; q < 4; q++) acc[ma][na][q] = 0.f;

    int am = t >> 1, ak = (t & 1) << 3;
    int bk = t >> 4, bn = (t & 15) << 2;

    float4 ra0, ra1, rbv;
    ra0 = *(const float4*)(Ab + (size_t)am * K + ak);
    ra1 = *(const float4*)(Ab + (size_t)am * K + ak + 4);
    rbv = *(const float4*)(Bb + (size_t)bk * N + bn);
    As[0][ak+0][am] = f2tf32(ra0.x); As[0][ak+1][am] = f2tf32(ra0.y);
    As[0][ak+2][am] = f2tf32(ra0.z); As[0][ak+3][am] = f2tf32(ra0.w);
    As[0][ak+4][am] = f2tf32(ra1.x); As[0][ak+5][am] = f2tf32(ra1.y);
    As[0][ak+6][am] = f2tf32(ra1.z); As[0][ak+7][am] = f2tf32(ra1.w);
    Bs[0][bk][bn+0] = f2tf32(rbv.x); Bs[0][bk][bn+1] = f2tf32(rbv.y);
    Bs[0][bk][bn+2] = f2tf32(rbv.z); Bs[0][bk][bn+3] = f2tf32(rbv.w);
    __syncthreads();

    int cur = 0;
    for (int kc = 0; kc < 16; kc++){
        if (kc + 1 < 16){
            int k0 = (kc + 1) << 4;
            ra0 = *(const float4*)(Ab + (size_t)am * K + k0 + ak);
            ra1 = *(const float4*)(Ab + (size_t)am * K + k0 + ak + 4);
            rbv = *(const float4*)(Bb + (size_t)(k0 + bk) * N + bn);
        }
#pragma unroll
        for (int ka = 0; ka < 2; ka++){
            int kb = ka << 3;
            uint32_t bf[2][2];
#pragma unroll
            for (int na = 0; na < 2; na++){
                int nn = wn*16 + na*8 + g;
                bf[na][0] = __float_as_uint(Bs[cur][kb+tg][nn]);
                bf[na][1] = __float_as_uint(Bs[cur][kb+tg+4][nn]);
            }
            uint32_t af[4][4];
#pragma unroll
            for (int ma = 0; ma < 4; ma++){
                int mm = wm*64 + ma*16 + g;
                af[ma][0] = __float_as_uint(As[cur][kb+tg][mm]);
                af[ma][1] = __float_as_uint(As[cur][kb+tg][mm+8]);
                af[ma][2] = __float_as_uint(As[cur][kb+tg+4][mm]);
                af[ma][3] = __float_as_uint(As[cur][kb+tg+4][mm+8]);
            }
#pragma unroll
            for (int ma = 0; ma < 4; ma++)
#pragma unroll
                for (int na = 0; na < 2; na++)
                    mma_tf32(acc[ma][na], af[ma][0], af[ma][1], af[ma][2], af[ma][3],
                             bf[na][0], bf[na][1]);
        }
        if (kc + 1 < 16){
            int nxt = cur ^ 1;
            As[nxt][ak+0][am] = f2tf32(ra0.x); As[nxt][ak+1][am] = f2tf32(ra0.y);
            As[nxt][ak+2][am] = f2tf32(ra0.z); As[nxt][ak+3][am] = f2tf32(ra0.w);
            As[nxt][ak+4][am] = f2tf32(ra1.x); As[nxt][ak+5][am] = f2tf32(ra1.y);
            As[nxt][ak+6][am] = f2tf32(ra1.z); As[nxt][ak+7][am] = f2tf32(ra1.w);
            Bs[nxt][bk][bn+0] = f2tf32(rbv.x); Bs[nxt][bk][bn+1] = f2tf32(rbv.y);
            Bs[nxt][bk][bn+2] = f2tf32(rbv.z); Bs[nxt][bk][bn+3] = f2tf32(rbv.w);
        }
        __syncthreads();
        cur ^= 1;
    }

    bool dokv = (n0 >= 512);
#pragma unroll
    for (int ma = 0; ma < 4; ma++){
        int r0 = m0 + wm*64 + ma*16 + g;
#pragma unroll
        for (int na = 0; na < 2; na++){
            int cb = n0 + wn*16 + na*8 + 2*tg;
            float2 v0 = make_float2(acc[ma][na][0], acc[ma][na][1]);
            float2 v1 = make_float2(acc[ma][na][2], acc[ma][na][3]);
            *(float2*)&C[(size_t)r0 * N + cb] = v0;
            *(float2*)&C[(size_t)(r0+8) * N + cb] = v1;
            if (dokv){
                *(__half2*)(KVH + (size_t)r0 * 1024 + (cb - 512)) =
                    __floats2half2_rn(v0.x, v0.y);
                *(__half2*)(KVH + (size_t)(r0+8) * 1024 + (cb - 512)) =
                    __floats2half2_rn(v1.x, v1.y);
            }
        }
    }
}

// ============================================================
// Top-64 nearest neighbors: smem-staged coors + 3-pass radix
// select on monotone fixed-point squared-distance keys
// (spread bins -> low smem-atomic contention).
// ============================================================
__global__ void __launch_bounds__(256) topk_kernel(const float* __restrict__ coors)
{
    __shared__ float c3[6144];            // staged coors; aliased by hist after keys
    int* hist = (int*)c3;
    __shared__ int wsum[8];
    __shared__ int sel_bin, sel_base;
    __shared__ int res_cnt, eq_cnt;
    __shared__ int res[64];
    __shared__ int eqlist[128];

    int t = threadIdx.x;
    int row = blockIdx.x;
    int b = row >> 11, i = row & 2047;
    const float* cbp = coors + (size_t)b * 2048 * 3;

    // stage batch coors: 6144 floats via float4
    for (int x = t; x < 1536; x += 256)
        *(float4*)&c3[x << 2] = *(const float4*)&cbp[x << 2];
    __syncthreads();

    float xi = c3[i*3+0], yi = c3[i*3+1], zi = c3[i*3+2];

    unsigned u[8];
#pragma unroll
    for (int r = 0; r < 8; r++){
        int c = r * 256 + t;
        float dx = xi - c3[c*3+0];
        float dy = yi - c3[c*3+1];
        float dz = zi - c3[c*3+2];
        float d2 = fmaf(dx, dx, fmaf(dy, dy, dz*dz));
        // monotone fixed-point key, 31 bits (step 2^-25 in d2 units)
        u[r] = (unsigned)fminf(d2 * 33554432.0f, 2147483520.0f);
    }
    __syncthreads();                      // c3 reads done; hist aliasing begins

    int k = 64;
    unsigned prefix = 0, pmask = 0;
#pragma unroll
    for (int p = 0; p < 3; p++){
        const int sh = (p == 0) ? 20 : (p == 1) ? 9 : 0;
        const int nbins = (p == 2) ? 512 : 2048;
        const unsigned bm = (unsigned)nbins - 1u;
        for (int x = t; x < nbins; x += 256) hist[x] = 0;
        __syncthreads();
#pragma unroll
        for (int r = 0; r < 8; r++)
            if ((u[r] & pmask) == prefix) atomicAdd(&hist[(u[r] >> sh) & bm], 1);
        __syncthreads();
        int per = nbins >> 8;
        int s = 0;
        for (int q = 0; q < per; q++) s += hist[t * per + q];
        int lane = t & 31, wid = t >> 5;
        int x = s;
#pragma unroll
        for (int o = 1; o < 32; o <<= 1){
            int y = __shfl_up_sync(0xffffffffu, x, o);
            if (lane >= o) x += y;
        }
        if (lane == 31) wsum[wid] = x;
        __syncthreads();
        int add = 0;
#pragma unroll
        for (int q = 0; q < 8; q++) if (q < wid) add += wsum[q];
        int incl = x + add;
        int excl = incl - s;
        if (excl < k && k <= incl){
            int running = excl;
            for (int q = 0; q < per; q++){
                int c = hist[t * per + q];
                if (running < k && k <= running + c){
                    sel_bin = t * per + q;
                    sel_base = running;
                    break;
                }
                running += c;
            }
        }
        __syncthreads();
        k -= sel_base;
        prefix |= ((unsigned)sel_bin) << sh;
        pmask |= bm << sh;
        __syncthreads();
    }
    unsigned D = prefix;
    if (t == 0){ res_cnt = 0; eq_cnt = 0; }
    __syncthreads();
#pragma unroll
    for (int r = 0; r < 8; r++){
        int c = r * 256 + t;
        if (u[r] < D){
            int p = atomicAdd(&res_cnt, 1);
            res[p] = c;
        } else if (u[r] == D){
            int p = atomicAdd(&eq_cnt, 1);
            if (p < 128) eqlist[p] = c;
        }
    }
    __syncthreads();
    if (t == 0){
        int ec = eq_cnt < 128 ? eq_cnt : 128;
        int base = res_cnt;
        for (int a = 0; a < k; a++){      // k smallest indices among ties
            int best = 0x7fffffff, bi = -1;
            for (int q = 0; q < ec; q++)
                if (eqlist[q] < best){ best = eqlist[q]; bi = q; }
            res[base + a] = best;
            if (bi >= 0) eqlist[bi] = 0x7fffffff;
        }
    }
    __syncthreads();
    if (t < 64) g_nb[row * 64 + t] = res[t];
}

// ============================================================
// Out-proj GEMM via tf32 MMA, split-K=2 over gridDim.z:
// slice z covers K cols [z*256,(z+1)*256); partials to P.
// ============================================================
__global__ void __launch_bounds__(256) sgemm_out_tc(
    const float* __restrict__ A,      // g_att (4096 x 512)
    const float* __restrict__ B,      // W_out (512 x 256)
    float* __restrict__ P)            // partials (2 x 4096 x 256)
{
    const int KS = 256, N = 256, LDA = 512;
    __shared__ float As[2][16][72];
    __shared__ float Bs[2][16][72];

    int t = threadIdx.x;
    int warp = t >> 5, lane = t & 31;
    int wm = warp & 1, wn = warp >> 1;
    int g = lane >> 2, tg = lane & 3;
    int z = blockIdx.z;
    int m0 = blockIdx.y * 64, n0 = blockIdx.x * 64;
    const float* Ab = A + (size_t)m0 * LDA + (size_t)z * KS;
    const float* Bb = B + (size_t)z * KS * N + n0;
    float* Pb = P + (size_t)z * NROWS * N;

    float acc[2][2][4];
#pragma unroll
    for (int ma = 0; ma < 2; ma++)
#pragma unroll
        for (int na = 0; na < 2; na++)
#pragma unroll
            for (int q = 0; q < 4; q++) acc[ma][na][q] = 0.f;

    int am = t >> 2, ak = (t & 3) << 2;
    int bk = t >> 4, bn = (t & 15) << 2;

    float4 rav, rbv;
    rav = *(const float4*)(Ab + (size_t)am * LDA + ak);
    rbv = *(const float4*)(Bb + (size_t)bk * N + bn);
    As[0][ak+0][am] = f2tf32(rav.x); As[0][ak+1][am] = f2tf32(rav.y);
    As[0][ak+2][am] = f2tf32(rav.z); As[0][ak+3][am] = f2tf32(rav.w);
    Bs[0][bk][bn+0] = f2tf32(rbv.x); Bs[0][bk][bn+1] = f2tf32(rbv.y);
    Bs[0][bk][bn+2] = f2tf32(rbv.z); Bs[0][bk][bn+3] = f2tf32(rbv.w);
    __syncthreads();

    int cur = 0;
    for (int kc = 0; kc < 16; kc++){
        if (kc + 1 < 16){
            int k0 = (kc + 1) << 4;
            rav = *(const float4*)(Ab + (size_t)am * LDA + k0 + ak);
            rbv = *(const float4*)(Bb + (size_t)(k0 + bk) * N + bn);
        }
#pragma unroll
        for (int ka = 0; ka < 2; ka++){
            int kb = ka << 3;
            uint32_t bf[2][2];
#pragma unroll
            for (int na = 0; na < 2; na++){
                int nn = wn*16 + na*8 + g;
                bf[na][0] = __float_as_uint(Bs[cur][kb+tg][nn]);
                bf[na][1] = __float_as_uint(Bs[cur][kb+tg+4][nn]);
            }
            uint32_t af[2][4];
#pragma unroll
            for (int ma = 0; ma < 2; ma++){
                int mm = wm*32 + ma*16 + g;
                af[ma][0] = __float_as_uint(As[cur][kb+tg][mm]);
                af[ma][1] = __float_as_uint(As[cur][kb+tg][mm+8]);
                af[ma][2] = __float_as_uint(As[cur][kb+tg+4][mm]);
                af[ma][3] = __float_as_uint(As[cur][kb+tg+4][mm+8]);
            }
#pragma unroll
            for (int ma = 0; ma < 2; ma++)
#pragma unroll
                for (int na = 0; na < 2; na++)
                    mma_tf32(acc[ma][na], af[ma][0], af[ma][1], af[ma][2], af[ma][3],
                             bf[na][0], bf[na][1]);
        }
        if (kc + 1 < 16){
            int nxt = cur ^ 1;
            As[nxt][ak+0][am] = f2tf32(rav.x); As[nxt][ak+1][am] = f2tf32(rav.y);
            As[nxt][ak+2][am] = f2tf32(rav.z); As[nxt][ak+3][am] = f2tf32(rav.w);
            Bs[nxt][bk][bn+0] = f2tf32(rbv.x); Bs[nxt][bk][bn+1] = f2tf32(rbv.y);
            Bs[nxt][bk][bn+2] = f2tf32(rbv.z); Bs[nxt][bk][bn+3] = f2tf32(rbv.w);
        }
        __syncthreads();
        cur ^= 1;
    }

#pragma unroll
    for (int ma = 0; ma < 2; ma++){
        int r0 = m0 + wm*32 + ma*16 + g;
#pragma unroll
        for (int na = 0; na < 2; na++){
            int cb = n0 + wn*16 + na*8 + 2*tg;
            *(float2*)&Pb[(size_t)r0 * N + cb] =
                make_float2(acc[ma][na][0], acc[ma][na][1]);
            *(float2*)&Pb[(size_t)(r0+8) * N + cb] =
                make_float2(acc[ma][na][2], acc[ma][na][3]);
        }
    }
}

// ============================================================
// split-K combine: out = P[0] + P[1] + bias  (4096x256 fp32)
// ============================================================
__global__ void __launch_bounds__(256) splitk2_add(
    const float* __restrict__ P, const float* __restrict__ bias,
    float* __restrict__ out)
{
    int idx = blockIdx.x * 256 + threadIdx.x;          // float4 index
    const size_t stride = (size_t)NROWS * 256 / 4;
    float4 a = ((const float4*)P)[idx];
    float4 b = ((const float4*)P)[idx + stride];
    float4 bb = ((const float4*)bias)[idx & 63];
    ((float4*)out)[idx] = make_float4(a.x+b.x+bb.x, a.y+b.y+bb.y,
                                      a.z+b.z+bb.z, a.w+b.w+bb.w);
}

// ============================================================
// Fused per-row attention kernel: one block per (b,i)
// ============================================================
__global__ void __launch_bounds__(256, 5) main_kernel(
    const float* __restrict__ coors,
    const float* __restrict__ edges,
    const float* __restrict__ W_e1, const float* __restrict__ b_e1,
    const float* __restrict__ W_e2, const float* __restrict__ b_e2,
    const float* __restrict__ W_c,  const float* __restrict__ b_c,
    const float* __restrict__ W_g,  const float* __restrict__ b_g,
    const float* __restrict__ combine, const float* __restrict__ cscale,
    float* __restrict__ out_coors)
{
    __shared__ float q_s[512];
    __shared__ __half2 cs_h[2048];        // (cos,sin) per (j, pair)
    __shared__ float in24[64][25];        // MLP inputs; reused as attn after MLP
    __shared__ float s_s[64][9];
    __shared__ float gs_s[64][9];
    __shared__ float ws_s[64][9];
    __shared__ float gate_s[64][9];
    __shared__ float reln[64][4];
    __shared__ float t_s[64];
    __shared__ float invf_s[32];
    __shared__ int   nb_s[64];
    __shared__ float we1[24*48];
    __shared__ float be1[48];
    __shared__ float we2[48*8];
    __shared__ float be2[8];
    __shared__ float wc[64], bc[8], wg[64], bg[8];
    __shared__ float delta_sm[3];

#define ATTN(j,h)   in24[j][h]

    int tid = threadIdx.x;
    int w = tid >> 5, l = tid & 31;
    int dq = l & 7, jg = l >> 3;
    int row = blockIdx.x;
    int b = row >> 11, i = row & 2047;
    const __half* kvb = g_kvh + (size_t)b * 2048 * 1024;

    for (int x = tid; x < 1152; x += 256) we1[x] = W_e1[x];
    for (int x = tid; x < 384;  x += 256) we2[x] = W_e2[x];
    if (tid < 48) be1[tid] = b_e1[tid];
    if (tid < 8){ be2[tid] = b_e2[tid]; bc[tid] = b_c[tid]; bg[tid] = b_g[tid]; }
    if (tid < 64){ wc[tid] = W_c[tid]; wg[tid] = W_g[tid]; }
    if (tid < 3) delta_sm[tid] = 0.f;
    {
        const float* qrow = g_qkv + (size_t)row * 1536;
        for (int x = tid; x < 512; x += 256) q_s[x] = qrow[x];
    }
    if (tid < 64) nb_s[tid] = g_nb[row * 64 + tid];
    __syncthreads();

    const float NEG_L2T_OVER32 = -0.41524101186092029f;  // -log2(10000)/32
    float scl = cscale[0];
    if (tid < 64){
        int j = nb_s[tid];
        const float* cp = coors + (size_t)b * 2048 * 3;
        float dx = cp[i*3+0] - cp[j*3+0];
        float dy = cp[i*3+1] - cp[j*3+1];
        float dz = cp[i*3+2] - cp[j*3+2];
        float d = sqrtf(dx*dx + dy*dy + dz*dz);
        t_s[tid] = fminf(d * 100.f, 5000.f);
        float inv = scl / fmaxf(d, 1e-8f);
        reln[tid][0] = dx * inv;
        reln[tid][1] = dy * inv;
        reln[tid][2] = dz * inv;
    } else if (tid >= 128 && tid < 160){
        invf_s[tid - 128] = exp2f((float)(tid - 128) * NEG_L2T_OVER32);
    }
    __syncthreads();

    // rotary (cos,sin) table on the FMA pipe
    for (int x = tid; x < 2048; x += 256){
        int j = x >> 5, li = x & 31;
        float ang = t_s[j] * invf_s[li];
        float sv, cv;
        fast_sincos(ang, &sv, &cv);
        cs_h[x] = __floats2half2_rn(cv, sv);
    }

    // gather edges: 4 threads per neighbor -> in24[j][8..23]
    {
        int j = tid >> 2, q4 = (tid & 3) << 2;
        const float* ep = edges + (((size_t)(b * 2048 + i)) * 2048 + (size_t)nb_s[j]) * 16 + q4;
        float4 ev = *(const float4*)ep;
        in24[j][8+q4+0] = ev.x; in24[j][8+q4+1] = ev.y;
        in24[j][8+q4+2] = ev.z; in24[j][8+q4+3] = ev.w;
    }
    __syncthreads();

    // k-pass: warp w = head w; lane (jg,dq): j = 4t+jg, dims dq*8..dq*8+7
    {
        float qreg[8];
#pragma unroll
        for (int x = 0; x < 8; x++) qreg[x] = q_s[w*64 + dq*8 + x];
#pragma unroll 4
        for (int t = 0; t < 16; t++){
            int j = t*4 + jg;
            const __half* kp = kvb + (size_t)nb_s[j] * 1024 + w*64 + dq*8;
            float4 kraw = *(const float4*)kp;
            const __half2* kh = (const __half2*)&kraw;
            float4 craw = *(const float4*)&cs_h[j*32 + dq*4];
            const __half2* ch = (const __half2*)&craw;
            float p = 0.f;
#pragma unroll
            for (int q = 0; q < 4; q++){
                float2 kv = __half22float2(kh[q]);
                float2 cs = __half22float2(ch[q]);
                float kr0 = kv.x*cs.x - kv.y*cs.y;
                float kr1 = fmaf(kv.y, cs.x, kv.x*cs.y);
                p = fmaf(qreg[2*q], kr0, p);
                p = fmaf(qreg[2*q+1], kr1, p);
            }
            p += __shfl_xor_sync(0xffffffffu, p, 1);
            p += __shfl_xor_sync(0xffffffffu, p, 2);
            p += __shfl_xor_sync(0xffffffffu, p, 4);
            if (dq == 0) in24[j][w] = p;
        }
    }
    for (int x = tid; x < 512; x += 256) s_s[x >> 3][x & 7] = be2[x & 7];
    __syncthreads();

    // edge MLP 24 -> 48 (GELU) -> 8, vectorized weights
    {
        int j = tid & 63, part = tid >> 6, hd0 = part * 12;
        float hid[12];
        {
            float4 b0 = *(const float4*)&be1[hd0];
            float4 b1 = *(const float4*)&be1[hd0+4];
            float4 b2 = *(const float4*)&be1[hd0+8];
            hid[0]=b0.x; hid[1]=b0.y; hid[2]=b0.z; hid[3]=b0.w;
            hid[4]=b1.x; hid[5]=b1.y; hid[6]=b1.z; hid[7]=b1.w;
            hid[8]=b2.x; hid[9]=b2.y; hid[10]=b2.z; hid[11]=b2.w;
        }
#pragma unroll
        for (int p = 0; p < 24; p++){
            float inp = in24[j][p];
            const float* wrow = &we1[p*48 + hd0];
            float4 w0 = *(const float4*)(wrow);
            float4 w1 = *(const float4*)(wrow+4);
            float4 w2 = *(const float4*)(wrow+8);
            hid[0]=fmaf(inp,w0.x,hid[0]); hid[1]=fmaf(inp,w0.y,hid[1]);
            hid[2]=fmaf(inp,w0.z,hid[2]); hid[3]=fmaf(inp,w0.w,hid[3]);
            hid[4]=fmaf(inp,w1.x,hid[4]); hid[5]=fmaf(inp,w1.y,hid[5]);
            hid[6]=fmaf(inp,w1.z,hid[6]); hid[7]=fmaf(inp,w1.w,hid[7]);
            hid[8]=fmaf(inp,w2.x,hid[8]); hid[9]=fmaf(inp,w2.y,hid[9]);
            hid[10]=fmaf(inp,w2.z,hid[10]); hid[11]=fmaf(inp,w2.w,hid[11]);
        }
#pragma unroll
        for (int hh = 0; hh < 12; hh++) hid[hh] = gelu_exact(hid[hh]);

        float acc[8];
#pragma unroll
        for (int h = 0; h < 8; h++) acc[h] = 0.f;
#pragma unroll
        for (int hh = 0; hh < 12; hh++){
            const float* urow = &we2[(hd0+hh)*8];
            float4 u0 = *(const float4*)(urow);
            float4 u1 = *(const float4*)(urow+4);
            float hv = hid[hh];
            acc[0]=fmaf(hv,u0.x,acc[0]); acc[1]=fmaf(hv,u0.y,acc[1]);
            acc[2]=fmaf(hv,u0.z,acc[2]); acc[3]=fmaf(hv,u0.w,acc[3]);
            acc[4]=fmaf(hv,u1.x,acc[4]); acc[5]=fmaf(hv,u1.y,acc[5]);
            acc[6]=fmaf(hv,u1.z,acc[6]); acc[7]=fmaf(hv,u1.w,acc[7]);
        }
#pragma unroll
        for (int h = 0; h < 8; h++) atomicAdd(&s_s[j][h], acc[h]);
    }
    __syncthreads();

    for (int x = tid; x < 512; x += 256){
        int jj = x >> 3, h = x & 7;
        gs_s[jj][h] = gelu_exact(s_s[jj][h]);
    }
    __syncthreads();
    for (int x = tid; x < 512; x += 256){
        int jj = x >> 3, h = x & 7;
        float cw = bc[h], gt = bg[h];
#pragma unroll
        for (int p = 0; p < 8; p++){
            cw = fmaf(gs_s[jj][p], wc[p*8 + h], cw);
            gt = fmaf(s_s[jj][p],  wg[p*8 + h], gt);
        }
        ws_s[jj][h] = cw;
        gate_s[jj][h] = fast_tanh(gt);
    }
    __syncthreads();

    // dual softmax over j per head (warp w)
    {
        float sa = s_s[l][w], sb = s_s[l+32][w];
        float m = fmaxf(sa, sb);
#pragma unroll
        for (int o = 16; o > 0; o >>= 1) m = fmaxf(m, __shfl_xor_sync(0xffffffffu, m, o));
        float ea = __expf(sa - m), eb = __expf(sb - m);
        float sum = ea + eb;
#pragma unroll
        for (int o = 16; o > 0; o >>= 1) sum += __shfl_xor_sync(0xffffffffu, sum, o);
        float inv = 1.f / sum;
        float at_a = ea * inv, at_b = eb * inv;

        float ca = ws_s[l][w], cb2 = ws_s[l+32][w];
        float m2 = fmaxf(ca, cb2);
#pragma unroll
        for (int o = 16; o > 0; o >>= 1) m2 = fmaxf(m2, __shfl_xor_sync(0xffffffffu, m2, o));
        float e2a = __expf(ca - m2), e2b = __expf(cb2 - m2);
        float sum2 = e2a + e2b;
#pragma unroll
        for (int o = 16; o > 0; o >>= 1) sum2 += __shfl_xor_sync(0xffffffffu, sum2, o);
        float inv2 = 1.f / sum2;
        __syncthreads();
        ATTN(l, w)    = at_a;
        ATTN(l+32, w) = at_b;
        ws_s[l][w]    = e2a * inv2 * gate_s[l][w];
        ws_s[l+32][w] = e2b * inv2 * gate_s[l+32][w];
    }
    __syncthreads();

    // coordinate delta
    {
        float wa = ws_s[l][w], wb = ws_s[l+32][w];
        float d0 = wa * reln[l][0] + wb * reln[l+32][0];
        float d1 = wa * reln[l][1] + wb * reln[l+32][1];
        float d2 = wa * reln[l][2] + wb * reln[l+32][2];
#pragma unroll
        for (int o = 16; o > 0; o >>= 1){
            d0 += __shfl_xor_sync(0xffffffffu, d0, o);
            d1 += __shfl_xor_sync(0xffffffffu, d1, o);
            d2 += __shfl_xor_sync(0xffffffffu, d2, o);
        }
        if (l == 0){
            float cmb = combine[w];
            atomicAdd(&delta_sm[0], d0 * cmb);
            atomicAdd(&delta_sm[1], d1 * cmb);
            atomicAdd(&delta_sm[2], d2 * cmb);
        }
    }

    // v-pass
    {
        float acc[8];
#pragma unroll
        for (int x = 0; x < 8; x++) acc[x] = 0.f;
#pragma unroll 4
        for (int t = 0; t < 16; t++){
            int j = t*4 + jg;
            float a = ATTN(j, w);
            const __half* vp = kvb + (size_t)nb_s[j] * 1024 + 512 + w*64 + dq*8;
            float4 vraw = *(const float4*)vp;
            const __half2* vh = (const __half2*)&vraw;
            float4 craw = *(const float4*)&cs_h[j*32 + dq*4];
            const __half2* ch = (const __half2*)&craw;
#pragma unroll
            for (int q = 0; q < 4; q++){
                float2 vv = __half22float2(vh[q]);
                float2 cs = __half22float2(ch[q]);
                acc[2*q]   = fmaf(a, vv.x*cs.x - vv.y*cs.y, acc[2*q]);
                acc[2*q+1] = fmaf(a, fmaf(vv.y, cs.x, vv.x*cs.y), acc[2*q+1]);
            }
        }
#pragma unroll
        for (int x = 0; x < 8; x++){
            acc[x] += __shfl_xor_sync(0xffffffffu, acc[x], 8);
            acc[x] += __shfl_xor_sync(0xffffffffu, acc[x], 16);
        }
        if (jg == 0){
            float4* po = (float4*)&g_att[(size_t)row * 512 + w*64 + dq*8];
            po[0] = make_float4(acc[0], acc[1], acc[2], acc[3]);
            po[1] = make_float4(acc[4], acc[5], acc[6], acc[7]);
        }
    }
    __syncthreads();
    if (tid < 3) out_coors[row * 3 + tid] = delta_sm[tid];
}

// ============================================================
extern "C" void kernel_launch(void* const* d_in, const int* in_sizes, int n_in,
                              void* d_out, int out_size)
{
    const float* feats   = (const float*)d_in[0];
    const float* coors   = (const float*)d_in[1];
    const float* edges   = (const float*)d_in[2];
    const float* W_qkv   = (const float*)d_in[3];
    const float* W_out   = (const float*)d_in[4];
    const float* b_out   = (const float*)d_in[5];
    const float* W_e1    = (const float*)d_in[6];
    const float* b_e1    = (const float*)d_in[7];
    const float* W_e2    = (const float*)d_in[8];
    const float* b_e2    = (const float*)d_in[9];
    const float* W_c     = (const float*)d_in[10];
    const float* b_c     = (const float*)d_in[11];
    const float* W_g     = (const float*)d_in[12];
    const float* b_g     = (const float*)d_in[13];
    const float* combine = (const float*)d_in[14];
    const float* cscale  = (const float*)d_in[15];
    float* out = (float*)d_out;

    void *p_qkv = 0, *p_att = 0, *p_kvh = 0;
    cudaGetSymbolAddress(&p_qkv, g_qkv);
    cudaGetSymbolAddress(&p_att, g_att);
    cudaGetSymbolAddress(&p_kvh, g_kvh);

    // 1) tf32 QKV GEMM, then top-64 select (smem-staged, spread radix bins)
    qkv_tc_kernel<<<768, 256>>>(feats, W_qkv, (float*)p_qkv, (__half*)p_kvh);
    topk_kernel<<<4096, 256>>>(coors);

    // 2) fused attention; writes g_att and coors_delta region of d_out
    main_kernel<<<4096, 256>>>(coors, edges,
        W_e1, b_e1, W_e2, b_e2, W_c, b_c, W_g, b_g,
        combine, cscale, out + 2*2048*256);

    // 3) output projection: tf32 MMA split-K=2 into g_qkv scratch, then combine
    sgemm_out_tc<<<dim3(256/64, 4096/64, 2), 256>>>(
        (const float*)p_att, W_out, (float*)p_qkv);
    splitk2_add<<<1024, 256>>>((const float*)p_qkv, b_out, out);
}

// round 16
// speedup vs baseline: 1.0152x; 1.0152x over previous
#include <cuda_runtime.h>
#include <cuda_fp16.h>
#include <math.h>
#include <stdint.h>

// Problem constants: b=2, n=2048, d=256, e=16, h=8, dh=64, inner=512, nn=64
#define NROWS 4096

// ---- scratch (static device globals; no runtime allocation) ----
static __device__ float  g_qkv[NROWS * 1536];   // q|k|v per row (fp32)
static __device__ __half g_kvh[NROWS * 1024];   // k|v per row (fp16) for gathers
static __device__ float  g_att[NROWS * 512];    // attention feature output
static __device__ int    g_nb[NROWS * 64];      // neighbor indices

__device__ __forceinline__ float gelu_exact(float x){
    return 0.5f * x * (1.0f + erff(x * 0.7071067811865475f));
}

__device__ __forceinline__ float fast_tanh(float x){
    float r;
    asm("tanh.approx.f32 %0, %1;" : "=f"(r) : "f"(x));
    return r;
}

// FMA-pipe sincos: quadrant reduction + minimax polys (no MUFU).
__device__ __forceinline__ void fast_sincos(float ang, float* sv, float* cv){
    float nq = rintf(ang * 0.63661977236758134f);   // 2/pi
    int qi = (int)nq;
    float r = fmaf(nq, -1.5707963705062866f, ang);
    r = fmaf(nq, 4.3711390001862428e-8f, r);
    float r2 = r * r;
    float sp = fmaf(fmaf(fmaf(-1.9515296e-4f, r2, 8.3321638e-3f), r2,
                         -1.6666654e-1f), r2, 1.f) * r;
    float cp = fmaf(fmaf(fmaf(-1.3853704e-3f, r2, 4.1663683e-2f), r2,
                         -4.9999905e-1f), r2, 1.f);
    float s_ = (qi & 1) ? cp : sp;
    float c_ = (qi & 1) ? sp : cp;
    if (qi & 2) s_ = -s_;
    if ((qi + 1) & 2) c_ = -c_;
    *sv = s_; *cv = c_;
}

__device__ __forceinline__ float f2tf32(float x){
    uint32_t u;
    asm("cvt.rna.tf32.f32 %0, %1;" : "=r"(u) : "f"(x));
    return __uint_as_float(u);
}

__device__ __forceinline__ void mma_tf32(float c[4], uint32_t a0, uint32_t a1,
                                         uint32_t a2, uint32_t a3,
                                         uint32_t b0, uint32_t b1){
    asm volatile(
        "mma.sync.aligned.m16n8k8.row.col.f32.tf32.tf32.f32 "
        "{%0,%1,%2,%3}, {%4,%5,%6,%7}, {%8,%9}, {%0,%1,%2,%3};"
        : "+f"(c[0]), "+f"(c[1]), "+f"(c[2]), "+f"(c[3])
        : "r"(a0), "r"(a1), "r"(a2), "r"(a3), "r"(b0), "r"(b1));
}

// ============================================================
// QKV GEMM: 128x64 tile tf32 MMA, (4096,256)@(256,1536);
// epilogue packs fp16 k|v (cols >= 512).
// ============================================================
__global__ void __launch_bounds__(256) qkv_tc_kernel(
    const float* __restrict__ A, const float* __restrict__ B,
    float* __restrict__ C, __half* __restrict__ KVH)
{
    const int K = 256, N = 1536;
    __shared__ float As[2][16][136];
    __shared__ float Bs[2][16][72];

    int t = threadIdx.x;
    int warp = t >> 5, lane = t & 31;
    int wm = warp & 1, wn = warp >> 1;
    int g = lane >> 2, tg = lane & 3;
    int bx = blockIdx.x;
    int m0 = (bx / 24) * 128, n0 = (bx % 24) * 64;
    const float* Ab = A + (size_t)m0 * K;
    const float* Bb = B + n0;

    float acc[4][2][4];
#pragma unroll
    for (int ma = 0; ma < 4; ma++)
#pragma unroll
        for (int na = 0; na < 2; na++)
#pragma unroll
            for (int q = 0; q < 4; q++) acc[ma][na][q] = 0.f;

    int am = t >> 1, ak = (t & 1) << 3;
    int bk = t >> 4, bn = (t & 15) << 2;

    float4 ra0, ra1, rbv;
    ra0 = *(const float4*)(Ab + (size_t)am * K + ak);
    ra1 = *(const float4*)(Ab + (size_t)am * K + ak + 4);
    rbv = *(const float4*)(Bb + (size_t)bk * N + bn);
    As[0][ak+0][am] = f2tf32(ra0.x); As[0][ak+1][am] = f2tf32(ra0.y);
    As[0][ak+2][am] = f2tf32(ra0.z); As[0][ak+3][am] = f2tf32(ra0.w);
    As[0][ak+4][am] = f2tf32(ra1.x); As[0][ak+5][am] = f2tf32(ra1.y);
    As[0][ak+6][am] = f2tf32(ra1.z); As[0][ak+7][am] = f2tf32(ra1.w);
    Bs[0][bk][bn+0] = f2tf32(rbv.x); Bs[0][bk][bn+1] = f2tf32(rbv.y);
    Bs[0][bk][bn+2] = f2tf32(rbv.z); Bs[0][bk][bn+3] = f2tf32(rbv.w);
    __syncthreads();

    int cur = 0;
    for (int kc = 0; kc < 16; kc++){
        if (kc + 1 < 16){
            int k0 = (kc + 1) << 4;
            ra0 = *(const float4*)(Ab + (size_t)am * K + k0 + ak);
            ra1 = *(const float4*)(Ab + (size_t)am * K + k0 + ak + 4);
            rbv = *(const float4*)(Bb + (size_t)(k0 + bk) * N + bn);
        }
#pragma unroll
        for (int ka = 0; ka < 2; ka++){
            int kb = ka << 3;
            uint32_t bf[2][2];
#pragma unroll
            for (int na = 0; na < 2; na++){
                int nn = wn*16 + na*8 + g;
                bf[na][0] = __float_as_uint(Bs[cur][kb+tg][nn]);
                bf[na][1] = __float_as_uint(Bs[cur][kb+tg+4][nn]);
            }
            uint32_t af[4][4];
#pragma unroll
            for (int ma = 0; ma < 4; ma++){
                int mm = wm*64 + ma*16 + g;
                af[ma][0] = __float_as_uint(As[cur][kb+tg][mm]);
                af[ma][1] = __float_as_uint(As[cur][kb+tg][mm+8]);
                af[ma][2] = __float_as_uint(As[cur][kb+tg+4][mm]);
                af[ma][3] = __float_as_uint(As[cur][kb+tg+4][mm+8]);
            }
#pragma unroll
            for (int ma = 0; ma < 4; ma++)
#pragma unroll
                for (int na = 0; na < 2; na++)
                    mma_tf32(acc[ma][na], af[ma][0], af[ma][1], af[ma][2], af[ma][3],
                             bf[na][0], bf[na][1]);
        }
        if (kc + 1 < 16){
            int nxt = cur ^ 1;
            As[nxt][ak+0][am] = f2tf32(ra0.x); As[nxt][ak+1][am] = f2tf32(ra0.y);
            As[nxt][ak+2][am] = f2tf32(ra0.z); As[nxt][ak+3][am] = f2tf32(ra0.w);
            As[nxt][ak+4][am] = f2tf32(ra1.x); As[nxt][ak+5][am] = f2tf32(ra1.y);
            As[nxt][ak+6][am] = f2tf32(ra1.z); As[nxt][ak+7][am] = f2tf32(ra1.w);
            Bs[nxt][bk][bn+0] = f2tf32(rbv.x); Bs[nxt][bk][bn+1] = f2tf32(rbv.y);
            Bs[nxt][bk][bn+2] = f2tf32(rbv.z); Bs[nxt][bk][bn+3] = f2tf32(rbv.w);
        }
        __syncthreads();
        cur ^= 1;
    }

    bool dokv = (n0 >= 512);
#pragma unroll
    for (int ma = 0; ma < 4; ma++){
        int r0 = m0 + wm*64 + ma*16 + g;
#pragma unroll
        for (int na = 0; na < 2; na++){
            int cb = n0 + wn*16 + na*8 + 2*tg;
            float2 v0 = make_float2(acc[ma][na][0], acc[ma][na][1]);
            float2 v1 = make_float2(acc[ma][na][2], acc[ma][na][3]);
            *(float2*)&C[(size_t)r0 * N + cb] = v0;
            *(float2*)&C[(size_t)(r0+8) * N + cb] = v1;
            if (dokv){
                *(__half2*)(KVH + (size_t)r0 * 1024 + (cb - 512)) =
                    __floats2half2_rn(v0.x, v0.y);
                *(__half2*)(KVH + (size_t)(r0+8) * 1024 + (cb - 512)) =
                    __floats2half2_rn(v1.x, v1.y);
            }
        }
    }
}

// ============================================================
// Top-64 nearest neighbors: 3-pass radix select on squared-dist
// fp32 bit patterns (order-preserving). (R14 known-good version)
// ============================================================
__global__ void __launch_bounds__(256) topk_kernel(const float* __restrict__ coors)
{
    __shared__ int hist[2048];
    __shared__ int wsum[8];
    __shared__ int sel_bin, sel_base;
    __shared__ int res_cnt, eq_cnt;
    __shared__ int res[64];
    __shared__ int eqlist[128];

    int t = threadIdx.x;
    int row = blockIdx.x;
    int b = row >> 11, i = row & 2047;
    const float* cbp = coors + (size_t)b * 2048 * 3;
    float xi = cbp[i*3+0], yi = cbp[i*3+1], zi = cbp[i*3+2];

    unsigned u[8];
#pragma unroll
    for (int r = 0; r < 8; r++){
        int c = r * 256 + t;
        float dx = xi - cbp[c*3+0];
        float dy = yi - cbp[c*3+1];
        float dz = zi - cbp[c*3+2];
        u[r] = __float_as_uint(fmaf(dx, dx, fmaf(dy, dy, dz*dz)));
    }

    int k = 64;
    unsigned prefix = 0, pmask = 0;
#pragma unroll
    for (int p = 0; p < 3; p++){
        const int sh = (p == 0) ? 21 : (p == 1) ? 10 : 0;
        const int nbins = (p == 2) ? 1024 : 2048;
        const unsigned bm = (unsigned)nbins - 1u;
        for (int x = t; x < nbins; x += 256) hist[x] = 0;
        __syncthreads();
#pragma unroll
        for (int r = 0; r < 8; r++)
            if ((u[r] & pmask) == prefix) atomicAdd(&hist[(u[r] >> sh) & bm], 1);
        __syncthreads();
        int per = nbins >> 8;
        int s = 0;
        for (int q = 0; q < per; q++) s += hist[t * per + q];
        int lane = t & 31, wid = t >> 5;
        int x = s;
#pragma unroll
        for (int o = 1; o < 32; o <<= 1){
            int y = __shfl_up_sync(0xffffffffu, x, o);
            if (lane >= o) x += y;
        }
        if (lane == 31) wsum[wid] = x;
        __syncthreads();
        int add = 0;
#pragma unroll
        for (int q = 0; q < 8; q++) if (q < wid) add += wsum[q];
        int incl = x + add;
        int excl = incl - s;
        if (excl < k && k <= incl){
            int running = excl;
            for (int q = 0; q < per; q++){
                int c = hist[t * per + q];
                if (running < k && k <= running + c){
                    sel_bin = t * per + q;
                    sel_base = running;
                    break;
                }
                running += c;
            }
        }
        __syncthreads();
        k -= sel_base;
        prefix |= ((unsigned)sel_bin) << sh;
        pmask |= bm << sh;
        __syncthreads();
    }
    unsigned D = prefix;
    if (t == 0){ res_cnt = 0; eq_cnt = 0; }
    __syncthreads();
#pragma unroll
    for (int r = 0; r < 8; r++){
        int c = r * 256 + t;
        if (u[r] < D){
            int p = atomicAdd(&res_cnt, 1);
            res[p] = c;
        } else if (u[r] == D){
            int p = atomicAdd(&eq_cnt, 1);
            if (p < 128) eqlist[p] = c;
        }
    }
    __syncthreads();
    if (t == 0){
        int ec = eq_cnt < 128 ? eq_cnt : 128;
        int base = res_cnt;
        for (int a = 0; a < k; a++){      // k smallest indices among ties
            int best = 0x7fffffff, bi = -1;
            for (int q = 0; q < ec; q++)
                if (eqlist[q] < best){ best = eqlist[q]; bi = q; }
            res[base + a] = best;
            if (bi >= 0) eqlist[bi] = 0x7fffffff;
        }
    }
    __syncthreads();
    if (t < 64) g_nb[row * 64 + t] = res[t];
}

// ============================================================
// Out-proj GEMM via tf32 MMA: (4096,512)@(512,256)+bias -> out
// 32x64 tile, grid 4x128 = 512 blocks (grid-limited fix).
// ============================================================
__global__ void __launch_bounds__(256) sgemm_out_tc(
    const float* __restrict__ A,      // g_att (4096 x 512)
    const float* __restrict__ B,      // W_out (512 x 256)
    const float* __restrict__ bias,   // b_out (256)
    float* __restrict__ C)            // out (4096 x 256)
{
    const int K = 512, N = 256;
    __shared__ float As[2][16][40];   // [k][m], pad 40 (=8 mod 32)
    __shared__ float Bs[2][16][72];

    int t = threadIdx.x;
    int warp = t >> 5, lane = t & 31;
    int wm = warp & 1, wn = warp >> 1;         // 2 m-warps x 4 n-warps, warp tile 16x16
    int g = lane >> 2, tg = lane & 3;
    int m0 = blockIdx.y * 32, n0 = blockIdx.x * 64;
    const float* Ab = A + (size_t)m0 * K;
    const float* Bb = B + n0;

    float acc[2][4];
#pragma unroll
    for (int na = 0; na < 2; na++)
#pragma unroll
        for (int q = 0; q < 4; q++) acc[na][q] = 0.f;

    int am = t >> 3, ak = (t & 7) << 1;        // 32 rows x 16 k, float2 each
    int bk = t >> 4, bn = (t & 15) << 2;

    float2 rav;
    float4 rbv;
    rav = *(const float2*)(Ab + (size_t)am * K + ak);
    rbv = *(const float4*)(Bb + (size_t)bk * N + bn);
    As[0][ak+0][am] = f2tf32(rav.x); As[0][ak+1][am] = f2tf32(rav.y);
    Bs[0][bk][bn+0] = f2tf32(rbv.x); Bs[0][bk][bn+1] = f2tf32(rbv.y);
    Bs[0][bk][bn+2] = f2tf32(rbv.z); Bs[0][bk][bn+3] = f2tf32(rbv.w);
    __syncthreads();

    int cur = 0;
    for (int kc = 0; kc < 32; kc++){
        if (kc + 1 < 32){
            int k0 = (kc + 1) << 4;
            rav = *(const float2*)(Ab + (size_t)am * K + k0 + ak);
            rbv = *(const float4*)(Bb + (size_t)(k0 + bk) * N + bn);
        }
#pragma unroll
        for (int ka = 0; ka < 2; ka++){
            int kb = ka << 3;
            uint32_t bf[2][2];
#pragma unroll
            for (int na = 0; na < 2; na++){
                int nn = wn*16 + na*8 + g;
                bf[na][0] = __float_as_uint(Bs[cur][kb+tg][nn]);
                bf[na][1] = __float_as_uint(Bs[cur][kb+tg+4][nn]);
            }
            uint32_t af[4];
            {
                int mm = wm*16 + g;
                af[0] = __float_as_uint(As[cur][kb+tg][mm]);
                af[1] = __float_as_uint(As[cur][kb+tg][mm+8]);
                af[2] = __float_as_uint(As[cur][kb+tg+4][mm]);
                af[3] = __float_as_uint(As[cur][kb+tg+4][mm+8]);
            }
#pragma unroll
            for (int na = 0; na < 2; na++)
                mma_tf32(acc[na], af[0], af[1], af[2], af[3], bf[na][0], bf[na][1]);
        }
        if (kc + 1 < 32){
            int nxt = cur ^ 1;
            As[nxt][ak+0][am] = f2tf32(rav.x); As[nxt][ak+1][am] = f2tf32(rav.y);
            Bs[nxt][bk][bn+0] = f2tf32(rbv.x); Bs[nxt][bk][bn+1] = f2tf32(rbv.y);
            Bs[nxt][bk][bn+2] = f2tf32(rbv.z); Bs[nxt][bk][bn+3] = f2tf32(rbv.w);
        }
        __syncthreads();
        cur ^= 1;
    }

    {
        int r0 = m0 + wm*16 + g;
#pragma unroll
        for (int na = 0; na < 2; na++){
            int cb = n0 + wn*16 + na*8 + 2*tg;
            float b0 = bias[cb], b1 = bias[cb+1];
            *(float2*)&C[(size_t)r0 * N + cb] =
                make_float2(acc[na][0] + b0, acc[na][1] + b1);
            *(float2*)&C[(size_t)(r0+8) * N + cb] =
                make_float2(acc[na][2] + b0, acc[na][3] + b1);
        }
    }
}

// ============================================================
// Fused per-row attention kernel: one block per (b,i)
// ============================================================
__global__ void __launch_bounds__(256, 5) main_kernel(
    const float* __restrict__ coors,
    const float* __restrict__ edges,
    const float* __restrict__ W_e1, const float* __restrict__ b_e1,
    const float* __restrict__ W_e2, const float* __restrict__ b_e2,
    const float* __restrict__ W_c,  const float* __restrict__ b_c,
    const float* __restrict__ W_g,  const float* __restrict__ b_g,
    const float* __restrict__ combine, const float* __restrict__ cscale,
    float* __restrict__ out_coors)
{
    __shared__ float q_s[512];
    __shared__ __half2 cs_h[2048];        // (cos,sin) per (j, pair)
    __shared__ float in24[64][25];        // MLP inputs; reused as attn after MLP
    __shared__ float s_s[64][9];
    __shared__ float gs_s[64][9];
    __shared__ float ws_s[64][9];
    __shared__ float gate_s[64][9];
    __shared__ float reln[64][4];
    __shared__ float t_s[64];
    __shared__ float invf_s[32];
    __shared__ int   nb_s[64];
    __shared__ float we1[24*48];
    __shared__ float be1[48];
    __shared__ float we2[48*8];
    __shared__ float be2[8];
    __shared__ float wc[64], bc[8], wg[64], bg[8];
    __shared__ float delta_sm[3];

#define ATTN(j,h)   in24[j][h]

    int tid = threadIdx.x;
    int w = tid >> 5, l = tid & 31;
    int dq = l & 7, jg = l >> 3;
    int row = blockIdx.x;
    int b = row >> 11, i = row & 2047;
    const __half* kvb = g_kvh + (size_t)b * 2048 * 1024;

    for (int x = tid; x < 1152; x += 256) we1[x] = W_e1[x];
    for (int x = tid; x < 384;  x += 256) we2[x] = W_e2[x];
    if (tid < 48) be1[tid] = b_e1[tid];
    if (tid < 8){ be2[tid] = b_e2[tid]; bc[tid] = b_c[tid]; bg[tid] = b_g[tid]; }
    if (tid < 64){ wc[tid] = W_c[tid]; wg[tid] = W_g[tid]; }
    if (tid < 3) delta_sm[tid] = 0.f;
    {
        const float* qrow = g_qkv + (size_t)row * 1536;
        for (int x = tid; x < 512; x += 256) q_s[x] = qrow[x];
    }
    if (tid < 64) nb_s[tid] = g_nb[row * 64 + tid];
    __syncthreads();

    const float NEG_L2T_OVER32 = -0.41524101186092029f;  // -log2(10000)/32
    float scl = cscale[0];
    if (tid < 64){
        int j = nb_s[tid];
        const float* cp = coors + (size_t)b * 2048 * 3;
        float dx = cp[i*3+0] - cp[j*3+0];
        float dy = cp[i*3+1] - cp[j*3+1];
        float dz = cp[i*3+2] - cp[j*3+2];
        float d = sqrtf(dx*dx + dy*dy + dz*dz);
        t_s[tid] = fminf(d * 100.f, 5000.f);
        float inv = scl / fmaxf(d, 1e-8f);
        reln[tid][0] = dx * inv;
        reln[tid][1] = dy * inv;
        reln[tid][2] = dz * inv;
    } else if (tid >= 128 && tid < 160){
        invf_s[tid - 128] = exp2f((float)(tid - 128) * NEG_L2T_OVER32);
    }
    __syncthreads();

    // rotary (cos,sin) table on the FMA pipe
    for (int x = tid; x < 2048; x += 256){
        int j = x >> 5, li = x & 31;
        float ang = t_s[j] * invf_s[li];
        float sv, cv;
        fast_sincos(ang, &sv, &cv);
        cs_h[x] = __floats2half2_rn(cv, sv);
    }

    // gather edges: 4 threads per neighbor -> in24[j][8..23]
    {
        int j = tid >> 2, q4 = (tid & 3) << 2;
        const float* ep = edges + (((size_t)(b * 2048 + i)) * 2048 + (size_t)nb_s[j]) * 16 + q4;
        float4 ev = *(const float4*)ep;
        in24[j][8+q4+0] = ev.x; in24[j][8+q4+1] = ev.y;
        in24[j][8+q4+2] = ev.z; in24[j][8+q4+3] = ev.w;
    }
    __syncthreads();

    // k-pass: warp w = head w; lane (jg,dq): j = 4t+jg, dims dq*8..dq*8+7
    {
        float qreg[8];
#pragma unroll
        for (int x = 0; x < 8; x++) qreg[x] = q_s[w*64 + dq*8 + x];
#pragma unroll 4
        for (int t = 0; t < 16; t++){
            int j = t*4 + jg;
            const __half* kp = kvb + (size_t)nb_s[j] * 1024 + w*64 + dq*8;
            float4 kraw = *(const float4*)kp;
            const __half2* kh = (const __half2*)&kraw;
            float4 craw = *(const float4*)&cs_h[j*32 + dq*4];
            const __half2* ch = (const __half2*)&craw;
            float p = 0.f;
#pragma unroll
            for (int q = 0; q < 4; q++){
                float2 kv = __half22float2(kh[q]);
                float2 cs = __half22float2(ch[q]);
                float kr0 = kv.x*cs.x - kv.y*cs.y;
                float kr1 = fmaf(kv.y, cs.x, kv.x*cs.y);
                p = fmaf(qreg[2*q], kr0, p);
                p = fmaf(qreg[2*q+1], kr1, p);
            }
            p += __shfl_xor_sync(0xffffffffu, p, 1);
            p += __shfl_xor_sync(0xffffffffu, p, 2);
            p += __shfl_xor_sync(0xffffffffu, p, 4);
            if (dq == 0) in24[j][w] = p;
        }
    }
    for (int x = tid; x < 512; x += 256) s_s[x >> 3][x & 7] = be2[x & 7];
    __syncthreads();

    // edge MLP 24 -> 48 (GELU) -> 8, vectorized weights
    {
        int j = tid & 63, part = tid >> 6, hd0 = part * 12;
        float hid[12];
        {
            float4 b0 = *(const float4*)&be1[hd0];
            float4 b1 = *(const float4*)&be1[hd0+4];
            float4 b2 = *(const float4*)&be1[hd0+8];
            hid[0]=b0.x; hid[1]=b0.y; hid[2]=b0.z; hid[3]=b0.w;
            hid[4]=b1.x; hid[5]=b1.y; hid[6]=b1.z; hid[7]=b1.w;
            hid[8]=b2.x; hid[9]=b2.y; hid[10]=b2.z; hid[11]=b2.w;
        }
#pragma unroll
        for (int p = 0; p < 24; p++){
            float inp = in24[j][p];
            const float* wrow = &we1[p*48 + hd0];
            float4 w0 = *(const float4*)(wrow);
            float4 w1 = *(const float4*)(wrow+4);
            float4 w2 = *(const float4*)(wrow+8);
            hid[0]=fmaf(inp,w0.x,hid[0]); hid[1]=fmaf(inp,w0.y,hid[1]);
            hid[2]=fmaf(inp,w0.z,hid[2]); hid[3]=fmaf(inp,w0.w,hid[3]);
            hid[4]=fmaf(inp,w1.x,hid[4]); hid[5]=fmaf(inp,w1.y,hid[5]);
            hid[6]=fmaf(inp,w1.z,hid[6]); hid[7]=fmaf(inp,w1.w,hid[7]);
            hid[8]=fmaf(inp,w2.x,hid[8]); hid[9]=fmaf(inp,w2.y,hid[9]);
            hid[10]=fmaf(inp,w2.z,hid[10]); hid[11]=fmaf(inp,w2.w,hid[11]);
        }
#pragma unroll
        for (int hh = 0; hh < 12; hh++) hid[hh] = gelu_exact(hid[hh]);

        float acc[8];
#pragma unroll
        for (int h = 0; h < 8; h++) acc[h] = 0.f;
#pragma unroll
        for (int hh = 0; hh < 12; hh++){
            const float* urow = &we2[(hd0+hh)*8];
            float4 u0 = *(const float4*)(urow);
            float4 u1 = *(const float4*)(urow+4);
            float hv = hid[hh];
            acc[0]=fmaf(hv,u0.x,acc[0]); acc[1]=fmaf(hv,u0.y,acc[1]);
            acc[2]=fmaf(hv,u0.z,acc[2]); acc[3]=fmaf(hv,u0.w,acc[3]);
            acc[4]=fmaf(hv,u1.x,acc[4]); acc[5]=fmaf(hv,u1.y,acc[5]);
            acc[6]=fmaf(hv,u1.z,acc[6]); acc[7]=fmaf(hv,u1.w,acc[7]);
        }
#pragma unroll
        for (int h = 0; h < 8; h++) atomicAdd(&s_s[j][h], acc[h]);
    }
    __syncthreads();

    for (int x = tid; x < 512; x += 256){
        int jj = x >> 3, h = x & 7;
        gs_s[jj][h] = gelu_exact(s_s[jj][h]);
    }
    __syncthreads();
    for (int x = tid; x < 512; x += 256){
        int jj = x >> 3, h = x & 7;
        float cw = bc[h], gt = bg[h];
#pragma unroll
        for (int p = 0; p < 8; p++){
            cw = fmaf(gs_s[jj][p], wc[p*8 + h], cw);
            gt = fmaf(s_s[jj][p],  wg[p*8 + h], gt);
        }
        ws_s[jj][h] = cw;
        gate_s[jj][h] = fast_tanh(gt);
    }
    __syncthreads();

    // dual softmax over j per head (warp w)
    {
        float sa = s_s[l][w], sb = s_s[l+32][w];
        float m = fmaxf(sa, sb);
#pragma unroll
        for (int o = 16; o > 0; o >>= 1) m = fmaxf(m, __shfl_xor_sync(0xffffffffu, m, o));
        float ea = __expf(sa - m), eb = __expf(sb - m);
        float sum = ea + eb;
#pragma unroll
        for (int o = 16; o > 0; o >>= 1) sum += __shfl_xor_sync(0xffffffffu, sum, o);
        float inv = 1.f / sum;
        float at_a = ea * inv, at_b = eb * inv;

        float ca = ws_s[l][w], cb2 = ws_s[l+32][w];
        float m2 = fmaxf(ca, cb2);
#pragma unroll
        for (int o = 16; o > 0; o >>= 1) m2 = fmaxf(m2, __shfl_xor_sync(0xffffffffu, m2, o));
        float e2a = __expf(ca - m2), e2b = __expf(cb2 - m2);
        float sum2 = e2a + e2b;
#pragma unroll
        for (int o = 16; o > 0; o >>= 1) sum2 += __shfl_xor_sync(0xffffffffu, sum2, o);
        float inv2 = 1.f / sum2;
        __syncthreads();
        ATTN(l, w)    = at_a;
        ATTN(l+32, w) = at_b;
        ws_s[l][w]    = e2a * inv2 * gate_s[l][w];
        ws_s[l+32][w] = e2b * inv2 * gate_s[l+32][w];
    }
    __syncthreads();

    // coordinate delta
    {
        float wa = ws_s[l][w], wb = ws_s[l+32][w];
        float d0 = wa * reln[l][0] + wb * reln[l+32][0];
        float d1 = wa * reln[l][1] + wb * reln[l+32][1];
        float d2 = wa * reln[l][2] + wb * reln[l+32][2];
#pragma unroll
        for (int o = 16; o > 0; o >>= 1){
            d0 += __shfl_xor_sync(0xffffffffu, d0, o);
            d1 += __shfl_xor_sync(0xffffffffu, d1, o);
            d2 += __shfl_xor_sync(0xffffffffu, d2, o);
        }
        if (l == 0){
            float cmb = combine[w];
            atomicAdd(&delta_sm[0], d0 * cmb);
            atomicAdd(&delta_sm[1], d1 * cmb);
            atomicAdd(&delta_sm[2], d2 * cmb);
        }
    }

    // v-pass
    {
        float acc[8];
#pragma unroll
        for (int x = 0; x < 8; x++) acc[x] = 0.f;
#pragma unroll 4
        for (int t = 0; t < 16; t++){
            int j = t*4 + jg;
            float a = ATTN(j, w);
            const __half* vp = kvb + (size_t)nb_s[j] * 1024 + 512 + w*64 + dq*8;
            float4 vraw = *(const float4*)vp;
            const __half2* vh = (const __half2*)&vraw;
            float4 craw = *(const float4*)&cs_h[j*32 + dq*4];
            const __half2* ch = (const __half2*)&craw;
#pragma unroll
            for (int q = 0; q < 4; q++){
                float2 vv = __half22float2(vh[q]);
                float2 cs = __half22float2(ch[q]);
                acc[2*q]   = fmaf(a, vv.x*cs.x - vv.y*cs.y, acc[2*q]);
                acc[2*q+1] = fmaf(a, fmaf(vv.y, cs.x, vv.x*cs.y), acc[2*q+1]);
            }
        }
#pragma unroll
        for (int x = 0; x < 8; x++){
            acc[x] += __shfl_xor_sync(0xffffffffu, acc[x], 8);
            acc[x] += __shfl_xor_sync(0xffffffffu, acc[x], 16);
        }
        if (jg == 0){
            float4* po = (float4*)&g_att[(size_t)row * 512 + w*64 + dq*8];
            po[0] = make_float4(acc[0], acc[1], acc[2], acc[3]);
            po[1] = make_float4(acc[4], acc[5], acc[6], acc[7]);
        }
    }
    __syncthreads();
    if (tid < 3) out_coors[row * 3 + tid] = delta_sm[tid];
}

// ============================================================
extern "C" void kernel_launch(void* const* d_in, const int* in_sizes, int n_in,
                              void* d_out, int out_size)
{
    const float* feats   = (const float*)d_in[0];
    const float* coors   = (const float*)d_in[1];
    const float* edges   = (const float*)d_in[2];
    const float* W_qkv   = (const float*)d_in[3];
    const float* W_out   = (const float*)d_in[4];
    const float* b_out   = (const float*)d_in[5];
    const float* W_e1    = (const float*)d_in[6];
    const float* b_e1    = (const float*)d_in[7];
    const float* W_e2    = (const float*)d_in[8];
    const float* b_e2    = (const float*)d_in[9];
    const float* W_c     = (const float*)d_in[10];
    const float* b_c     = (const float*)d_in[11];
    const float* W_g     = (const float*)d_in[12];
    const float* b_g     = (const float*)d_in[13];
    const float* combine = (const float*)d_in[14];
    const float* cscale  = (const float*)d_in[15];
    float* out = (float*)d_out;

    void *p_qkv = 0, *p_att = 0, *p_kvh = 0;
    cudaGetSymbolAddress(&p_qkv, g_qkv);
    cudaGetSymbolAddress(&p_att, g_att);
    cudaGetSymbolAddress(&p_kvh, g_kvh);

    // 1) tf32 QKV GEMM, then top-64 select
    qkv_tc_kernel<<<768, 256>>>(feats, W_qkv, (float*)p_qkv, (__half*)p_kvh);
    topk_kernel<<<4096, 256>>>(coors);

    // 2) fused attention; writes g_att and coors_delta region of d_out
    main_kernel<<<4096, 256>>>(coors, edges,
        W_e1, b_e1, W_e2, b_e2, W_c, b_c, W_g, b_g,
        combine, cscale, out + 2*2048*256);

    // 3) output projection: tf32 MMA 32x64 tiles (512 blocks), bias fused
    sgemm_out_tc<<<dim3(256/64, 4096/32), 256>>>(
        (const float*)p_att, W_out, b_out, out);
}

// round 17
// speedup vs baseline: 1.0593x; 1.0434x over previous
#include <cuda_runtime.h>
#include <cuda_fp16.h>
#include <math.h>
#include <stdint.h>

// Problem constants: b=2, n=2048, d=256, e=16, h=8, dh=64, inner=512, nn=64
#define NROWS 4096

// ---- scratch (static device globals; no runtime allocation) ----
static __device__ float  g_qkv[NROWS * 1536];   // q|k|v per row (fp32)
static __device__ __half g_kvh[NROWS * 1024];   // k|v per row (fp16) for gathers
static __device__ float  g_att[NROWS * 512];    // attention feature output
static __device__ int    g_nb[NROWS * 64];      // neighbor indices

__device__ __forceinline__ float gelu_exact(float x){
    return 0.5f * x * (1.0f + erff(x * 0.7071067811865475f));
}

__device__ __forceinline__ float fast_tanh(float x){
    float r;
    asm("tanh.approx.f32 %0, %1;" : "=f"(r) : "f"(x));
    return r;
}

// FMA-pipe sincos: quadrant reduction + minimax polys (no MUFU).
__device__ __forceinline__ void fast_sincos(float ang, float* sv, float* cv){
    float nq = rintf(ang * 0.63661977236758134f);   // 2/pi
    int qi = (int)nq;
    float r = fmaf(nq, -1.5707963705062866f, ang);
    r = fmaf(nq, 4.3711390001862428e-8f, r);
    float r2 = r * r;
    float sp = fmaf(fmaf(fmaf(-1.9515296e-4f, r2, 8.3321638e-3f), r2,
                         -1.6666654e-1f), r2, 1.f) * r;
    float cp = fmaf(fmaf(fmaf(-1.3853704e-3f, r2, 4.1663683e-2f), r2,
                         -4.9999905e-1f), r2, 1.f);
    float s_ = (qi & 1) ? cp : sp;
    float c_ = (qi & 1) ? sp : cp;
    if (qi & 2) s_ = -s_;
    if ((qi + 1) & 2) c_ = -c_;
    *sv = s_; *cv = c_;
}

__device__ __forceinline__ float f2tf32(float x){
    uint32_t u;
    asm("cvt.rna.tf32.f32 %0, %1;" : "=r"(u) : "f"(x));
    return __uint_as_float(u);
}

__device__ __forceinline__ void mma_tf32(float c[4], uint32_t a0, uint32_t a1,
                                         uint32_t a2, uint32_t a3,
                                         uint32_t b0, uint32_t b1){
    asm volatile(
        "mma.sync.aligned.m16n8k8.row.col.f32.tf32.tf32.f32 "
        "{%0,%1,%2,%3}, {%4,%5,%6,%7}, {%8,%9}, {%0,%1,%2,%3};"
        : "+f"(c[0]), "+f"(c[1]), "+f"(c[2]), "+f"(c[3])
        : "r"(a0), "r"(a1), "r"(a2), "r"(a3), "r"(b0), "r"(b1));
}

// ============================================================
// QKV GEMM: 128x64 tile tf32 MMA, (4096,256)@(256,1536);
// epilogue packs fp16 k|v (cols >= 512).
// ============================================================
__global__ void __launch_bounds__(256) qkv_tc_kernel(
    const float* __restrict__ A, const float* __restrict__ B,
    float* __restrict__ C, __half* __restrict__ KVH)
{
    const int K = 256, N = 1536;
    __shared__ float As[2][16][136];
    __shared__ float Bs[2][16][72];

    int t = threadIdx.x;
    int warp = t >> 5, lane = t & 31;
    int wm = warp & 1, wn = warp >> 1;
    int g = lane >> 2, tg = lane & 3;
    int bx = blockIdx.x;
    int m0 = (bx / 24) * 128, n0 = (bx % 24) * 64;
    const float* Ab = A + (size_t)m0 * K;
    const float* Bb = B + n0;

    float acc[4][2][4];
#pragma unroll
    for (int ma = 0; ma < 4; ma++)
#pragma unroll
        for (int na = 0; na < 2; na++)
#pragma unroll
            for (int q = 0; q < 4; q++) acc[ma][na][q] = 0.f;

    int am = t >> 1, ak = (t & 1) << 3;
    int bk = t >> 4, bn = (t & 15) << 2;

    float4 ra0, ra1, rbv;
    ra0 = *(const float4*)(Ab + (size_t)am * K + ak);
    ra1 = *(const float4*)(Ab + (size_t)am * K + ak + 4);
    rbv = *(const float4*)(Bb + (size_t)bk * N + bn);
    As[0][ak+0][am] = f2tf32(ra0.x); As[0][ak+1][am] = f2tf32(ra0.y);
    As[0][ak+2][am] = f2tf32(ra0.z); As[0][ak+3][am] = f2tf32(ra0.w);
    As[0][ak+4][am] = f2tf32(ra1.x); As[0][ak+5][am] = f2tf32(ra1.y);
    As[0][ak+6][am] = f2tf32(ra1.z); As[0][ak+7][am] = f2tf32(ra1.w);
    Bs[0][bk][bn+0] = f2tf32(rbv.x); Bs[0][bk][bn+1] = f2tf32(rbv.y);
    Bs[0][bk][bn+2] = f2tf32(rbv.z); Bs[0][bk][bn+3] = f2tf32(rbv.w);
    __syncthreads();

    int cur = 0;
    for (int kc = 0; kc < 16; kc++){
        if (kc + 1 < 16){
            int k0 = (kc + 1) << 4;
            ra0 = *(const float4*)(Ab + (size_t)am * K + k0 + ak);
            ra1 = *(const float4*)(Ab + (size_t)am * K + k0 + ak + 4);
            rbv = *(const float4*)(Bb + (size_t)(k0 + bk) * N + bn);
        }
#pragma unroll
        for (int ka = 0; ka < 2; ka++){
            int kb = ka << 3;
            uint32_t bf[2][2];
#pragma unroll
            for (int na = 0; na < 2; na++){
                int nn = wn*16 + na*8 + g;
                bf[na][0] = __float_as_uint(Bs[cur][kb+tg][nn]);
                bf[na][1] = __float_as_uint(Bs[cur][kb+tg+4][nn]);
            }
            uint32_t af[4][4];
#pragma unroll
            for (int ma = 0; ma < 4; ma++){
                int mm = wm*64 + ma*16 + g;
                af[ma][0] = __float_as_uint(As[cur][kb+tg][mm]);
                af[ma][1] = __float_as_uint(As[cur][kb+tg][mm+8]);
                af[ma][2] = __float_as_uint(As[cur][kb+tg+4][mm]);
                af[ma][3] = __float_as_uint(As[cur][kb+tg+4][mm+8]);
            }
#pragma unroll
            for (int ma = 0; ma < 4; ma++)
#pragma unroll
                for (int na = 0; na < 2; na++)
                    mma_tf32(acc[ma][na], af[ma][0], af[ma][1], af[ma][2], af[ma][3],
                             bf[na][0], bf[na][1]);
        }
        if (kc + 1 < 16){
            int nxt = cur ^ 1;
            As[nxt][ak+0][am] = f2tf32(ra0.x); As[nxt][ak+1][am] = f2tf32(ra0.y);
            As[nxt][ak+2][am] = f2tf32(ra0.z); As[nxt][ak+3][am] = f2tf32(ra0.w);
            As[nxt][ak+4][am] = f2tf32(ra1.x); As[nxt][ak+5][am] = f2tf32(ra1.y);
            As[nxt][ak+6][am] = f2tf32(ra1.z); As[nxt][ak+7][am] = f2tf32(ra1.w);
            Bs[nxt][bk][bn+0] = f2tf32(rbv.x); Bs[nxt][bk][bn+1] = f2tf32(rbv.y);
            Bs[nxt][bk][bn+2] = f2tf32(rbv.z); Bs[nxt][bk][bn+3] = f2tf32(rbv.w);
        }
        __syncthreads();
        cur ^= 1;
    }

    bool dokv = (n0 >= 512);
#pragma unroll
    for (int ma = 0; ma < 4; ma++){
        int r0 = m0 + wm*64 + ma*16 + g;
#pragma unroll
        for (int na = 0; na < 2; na++){
            int cb = n0 + wn*16 + na*8 + 2*tg;
            float2 v0 = make_float2(acc[ma][na][0], acc[ma][na][1]);
            float2 v1 = make_float2(acc[ma][na][2], acc[ma][na][3]);
            *(float2*)&C[(size_t)r0 * N + cb] = v0;
            *(float2*)&C[(size_t)(r0+8) * N + cb] = v1;
            if (dokv){
                *(__half2*)(KVH + (size_t)r0 * 1024 + (cb - 512)) =
                    __floats2half2_rn(v0.x, v0.y);
                *(__half2*)(KVH + (size_t)(r0+8) * 1024 + (cb - 512)) =
                    __floats2half2_rn(v1.x, v1.y);
            }
        }
    }
}

// ============================================================
// Top-64 nearest neighbors, 2-phase select:
//  phase 0: 2048-bin histogram on top-11 bits of a monotone
//           fixed-point d^2 key -> rank-64 threshold bin
//  phase 1: emit below-bin candidates; exact (key,idx) rank
//           among the threshold bin's members (small list)
// coors staged in smem (float4), hist aliases the staging buf.
// ============================================================
__global__ void __launch_bounds__(256) topk_kernel(const float* __restrict__ coors)
{
    __shared__ float c3[6144];            // staged coors (24KB); hist aliases
    int* hist = (int*)c3;                 // 2048 bins
    __shared__ unsigned eqkey[512];
    __shared__ int      eqidx[512];
    __shared__ int wsum[8];
    __shared__ int sel_bin, sel_base;
    __shared__ int res_cnt, eq_cnt;
    __shared__ int res[64];

    int t = threadIdx.x;
    int row = blockIdx.x;
    int b = row >> 11, i = row & 2047;
    const float* cbp = coors + (size_t)b * 2048 * 3;

    // stage batch coors: 6144 floats via float4
    for (int x = t; x < 1536; x += 256)
        *(float4*)&c3[x << 2] = *(const float4*)&cbp[x << 2];
    __syncthreads();

    float xi = c3[i*3+0], yi = c3[i*3+1], zi = c3[i*3+2];

    unsigned u[8];
#pragma unroll
    for (int r = 0; r < 8; r++){
        int c = r * 256 + t;
        float dx = xi - c3[c*3+0];
        float dy = yi - c3[c*3+1];
        float dz = zi - c3[c*3+2];
        float d2 = fmaf(dx, dx, fmaf(dy, dy, dz*dz));
        // monotone fixed-point key, 31 bits (step 2^-25 in d2)
        u[r] = (unsigned)fminf(d2 * 33554432.0f, 2147483520.0f);
    }
    __syncthreads();                      // c3 reads done; hist aliasing begins

    // phase 0: histogram on top-11 bits (bin = d2 * 32)
    for (int x = t; x < 2048; x += 256) hist[x] = 0;
    __syncthreads();
#pragma unroll
    for (int r = 0; r < 8; r++) atomicAdd(&hist[u[r] >> 20], 1);
    __syncthreads();
    {
        int s = 0;
#pragma unroll
        for (int q = 0; q < 8; q++) s += hist[t * 8 + q];
        int lane = t & 31, wid = t >> 5;
        int x = s;
#pragma unroll
        for (int o = 1; o < 32; o <<= 1){
            int y = __shfl_up_sync(0xffffffffu, x, o);
            if (lane >= o) x += y;
        }
        if (lane == 31) wsum[wid] = x;
        __syncthreads();
        int add = 0;
#pragma unroll
        for (int q = 0; q < 8; q++) if (q < wid) add += wsum[q];
        int incl = x + add;
        int excl = incl - s;
        if (excl < 64 && 64 <= incl){
            int running = excl;
#pragma unroll
            for (int q = 0; q < 8; q++){
                int c = hist[t * 8 + q];
                if (running < 64 && 64 <= running + c){
                    sel_bin = t * 8 + q;
                    sel_base = running;
                    break;
                }
                running += c;
            }
        }
    }
    __syncthreads();
    unsigned B = (unsigned)sel_bin;
    int kprime = 64 - sel_base;

    if (t == 0){ res_cnt = 0; eq_cnt = 0; }
    __syncthreads();
#pragma unroll
    for (int r = 0; r < 8; r++){
        int c = r * 256 + t;
        unsigned bin = u[r] >> 20;
        if (bin < B){
            int p = atomicAdd(&res_cnt, 1);
            res[p] = c;
        } else if (bin == B){
            int p = atomicAdd(&eq_cnt, 1);
            if (p < 512){ eqkey[p] = u[r]; eqidx[p] = c; }
        }
    }
    __syncthreads();

    // exact rank among threshold-bin members by (key, idx)
    {
        int cnt = eq_cnt < 512 ? eq_cnt : 512;
        for (int e = t; e < cnt; e += 256){
            unsigned ke = eqkey[e];
            int ie = eqidx[e];
            int rank = 0;
            for (int q = 0; q < cnt; q++){
                unsigned kq = eqkey[q];
                rank += (kq < ke) || (kq == ke && eqidx[q] < ie);
            }
            if (rank < kprime) res[sel_base + rank] = ie;
        }
    }
    __syncthreads();
    if (t < 64) g_nb[row * 64 + t] = res[t];
}

// ============================================================
// Out-proj GEMM via tf32 MMA: (4096,512)@(512,256)+bias -> out
// 64x64 tile (R14 best-measured config).
// ============================================================
__global__ void __launch_bounds__(256) sgemm_out_tc(
    const float* __restrict__ A,      // g_att (4096 x 512)
    const float* __restrict__ B,      // W_out (512 x 256)
    const float* __restrict__ bias,   // b_out (256)
    float* __restrict__ C)            // out (4096 x 256)
{
    const int K = 512, N = 256;
    __shared__ float As[2][16][72];
    __shared__ float Bs[2][16][72];

    int t = threadIdx.x;
    int warp = t >> 5, lane = t & 31;
    int wm = warp & 1, wn = warp >> 1;         // 2 m-warps x 4 n-warps, warp tile 32x16
    int g = lane >> 2, tg = lane & 3;
    int m0 = blockIdx.y * 64, n0 = blockIdx.x * 64;
    const float* Ab = A + (size_t)m0 * K;
    const float* Bb = B + n0;

    float acc[2][2][4];
#pragma unroll
    for (int ma = 0; ma < 2; ma++)
#pragma unroll
        for (int na = 0; na < 2; na++)
#pragma unroll
            for (int q = 0; q < 4; q++) acc[ma][na][q] = 0.f;

    int am = t >> 2, ak = (t & 3) << 2;        // 64 rows x 16 k, float4 each
    int bk = t >> 4, bn = (t & 15) << 2;

    float4 rav, rbv;
    rav = *(const float4*)(Ab + (size_t)am * K + ak);
    rbv = *(const float4*)(Bb + (size_t)bk * N + bn);
    As[0][ak+0][am] = f2tf32(rav.x); As[0][ak+1][am] = f2tf32(rav.y);
    As[0][ak+2][am] = f2tf32(rav.z); As[0][ak+3][am] = f2tf32(rav.w);
    Bs[0][bk][bn+0] = f2tf32(rbv.x); Bs[0][bk][bn+1] = f2tf32(rbv.y);
    Bs[0][bk][bn+2] = f2tf32(rbv.z); Bs[0][bk][bn+3] = f2tf32(rbv.w);
    __syncthreads();

    int cur = 0;
    for (int kc = 0; kc < 32; kc++){
        if (kc + 1 < 32){
            int k0 = (kc + 1) << 4;
            rav = *(const float4*)(Ab + (size_t)am * K + k0 + ak);
            rbv = *(const float4*)(Bb + (size_t)(k0 + bk) * N + bn);
        }
#pragma unroll
        for (int ka = 0; ka < 2; ka++){
            int kb = ka << 3;
            uint32_t bf[2][2];
#pragma unroll
            for (int na = 0; na < 2; na++){
                int nn = wn*16 + na*8 + g;
                bf[na][0] = __float_as_uint(Bs[cur][kb+tg][nn]);
                bf[na][1] = __float_as_uint(Bs[cur][kb+tg+4][nn]);
            }
            uint32_t af[2][4];
#pragma unroll
            for (int ma = 0; ma < 2; ma++){
                int mm = wm*32 + ma*16 + g;
                af[ma][0] = __float_as_uint(As[cur][kb+tg][mm]);
                af[ma][1] = __float_as_uint(As[cur][kb+tg][mm+8]);
                af[ma][2] = __float_as_uint(As[cur][kb+tg+4][mm]);
                af[ma][3] = __float_as_uint(As[cur][kb+tg+4][mm+8]);
            }
#pragma unroll
            for (int ma = 0; ma < 2; ma++)
#pragma unroll
                for (int na = 0; na < 2; na++)
                    mma_tf32(acc[ma][na], af[ma][0], af[ma][1], af[ma][2], af[ma][3],
                             bf[na][0], bf[na][1]);
        }
        if (kc + 1 < 32){
            int nxt = cur ^ 1;
            As[nxt][ak+0][am] = f2tf32(rav.x); As[nxt][ak+1][am] = f2tf32(rav.y);
            As[nxt][ak+2][am] = f2tf32(rav.z); As[nxt][ak+3][am] = f2tf32(rav.w);
            Bs[nxt][bk][bn+0] = f2tf32(rbv.x); Bs[nxt][bk][bn+1] = f2tf32(rbv.y);
            Bs[nxt][bk][bn+2] = f2tf32(rbv.z); Bs[nxt][bk][bn+3] = f2tf32(rbv.w);
        }
        __syncthreads();
        cur ^= 1;
    }

#pragma unroll
    for (int ma = 0; ma < 2; ma++){
        int r0 = m0 + wm*32 + ma*16 + g;
#pragma unroll
        for (int na = 0; na < 2; na++){
            int cb = n0 + wn*16 + na*8 + 2*tg;
            float b0 = bias[cb], b1 = bias[cb+1];
            *(float2*)&C[(size_t)r0 * N + cb] =
                make_float2(acc[ma][na][0] + b0, acc[ma][na][1] + b1);
            *(float2*)&C[(size_t)(r0+8) * N + cb] =
                make_float2(acc[ma][na][2] + b0, acc[ma][na][3] + b1);
        }
    }
}

// ============================================================
// Fused per-row attention kernel: one block per (b,i)
// ============================================================
__global__ void __launch_bounds__(256, 5) main_kernel(
    const float* __restrict__ coors,
    const float* __restrict__ edges,
    const float* __restrict__ W_e1, const float* __restrict__ b_e1,
    const float* __restrict__ W_e2, const float* __restrict__ b_e2,
    const float* __restrict__ W_c,  const float* __restrict__ b_c,
    const float* __restrict__ W_g,  const float* __restrict__ b_g,
    const float* __restrict__ combine, const float* __restrict__ cscale,
    float* __restrict__ out_coors)
{
    __shared__ float q_s[512];
    __shared__ __half2 cs_h[2048];        // (cos,sin) per (j, pair)
    __shared__ float in24[64][25];        // MLP inputs; reused as attn after MLP
    __shared__ float s_s[64][9];
    __shared__ float gs_s[64][9];
    __shared__ float ws_s[64][9];
    __shared__ float gate_s[64][9];
    __shared__ float reln[64][4];
    __shared__ float t_s[64];
    __shared__ float invf_s[32];
    __shared__ int   nb_s[64];
    __shared__ float we1[24*48];
    __shared__ float be1[48];
    __shared__ float we2[48*8];
    __shared__ float be2[8];
    __shared__ float wc[64], bc[8], wg[64], bg[8];
    __shared__ float delta_sm[3];

#define ATTN(j,h)   in24[j][h]

    int tid = threadIdx.x;
    int w = tid >> 5, l = tid & 31;
    int dq = l & 7, jg = l >> 3;
    int row = blockIdx.x;
    int b = row >> 11, i = row & 2047;
    const __half* kvb = g_kvh + (size_t)b * 2048 * 1024;

    for (int x = tid; x < 1152; x += 256) we1[x] = W_e1[x];
    for (int x = tid; x < 384;  x += 256) we2[x] = W_e2[x];
    if (tid < 48) be1[tid] = b_e1[tid];
    if (tid < 8){ be2[tid] = b_e2[tid]; bc[tid] = b_c[tid]; bg[tid] = b_g[tid]; }
    if (tid < 64){ wc[tid] = W_c[tid]; wg[tid] = W_g[tid]; }
    if (tid < 3) delta_sm[tid] = 0.f;
    {
        const float* qrow = g_qkv + (size_t)row * 1536;
        for (int x = tid; x < 512; x += 256) q_s[x] = qrow[x];
    }
    if (tid < 64) nb_s[tid] = g_nb[row * 64 + tid];
    __syncthreads();

    const float NEG_L2T_OVER32 = -0.41524101186092029f;  // -log2(10000)/32
    float scl = cscale[0];
    if (tid < 64){
        int j = nb_s[tid];
        const float* cp = coors + (size_t)b * 2048 * 3;
        float dx = cp[i*3+0] - cp[j*3+0];
        float dy = cp[i*3+1] - cp[j*3+1];
        float dz = cp[i*3+2] - cp[j*3+2];
        float d = sqrtf(dx*dx + dy*dy + dz*dz);
        t_s[tid] = fminf(d * 100.f, 5000.f);
        float inv = scl / fmaxf(d, 1e-8f);
        reln[tid][0] = dx * inv;
        reln[tid][1] = dy * inv;
        reln[tid][2] = dz * inv;
    } else if (tid >= 128 && tid < 160){
        invf_s[tid - 128] = exp2f((float)(tid - 128) * NEG_L2T_OVER32);
    }
    __syncthreads();

    // rotary (cos,sin) table on the FMA pipe
    for (int x = tid; x < 2048; x += 256){
        int j = x >> 5, li = x & 31;
        float ang = t_s[j] * invf_s[li];
        float sv, cv;
        fast_sincos(ang, &sv, &cv);
        cs_h[x] = __floats2half2_rn(cv, sv);
    }

    // gather edges: 4 threads per neighbor -> in24[j][8..23]
    {
        int j = tid >> 2, q4 = (tid & 3) << 2;
        const float* ep = edges + (((size_t)(b * 2048 + i)) * 2048 + (size_t)nb_s[j]) * 16 + q4;
        float4 ev = *(const float4*)ep;
        in24[j][8+q4+0] = ev.x; in24[j][8+q4+1] = ev.y;
        in24[j][8+q4+2] = ev.z; in24[j][8+q4+3] = ev.w;
    }
    __syncthreads();

    // k-pass: warp w = head w; lane (jg,dq): j = 4t+jg, dims dq*8..dq*8+7
    {
        float qreg[8];
#pragma unroll
        for (int x = 0; x < 8; x++) qreg[x] = q_s[w*64 + dq*8 + x];
#pragma unroll 4
        for (int t = 0; t < 16; t++){
            int j = t*4 + jg;
            const __half* kp = kvb + (size_t)nb_s[j] * 1024 + w*64 + dq*8;
            float4 kraw = *(const float4*)kp;
            const __half2* kh = (const __half2*)&kraw;
            float4 craw = *(const float4*)&cs_h[j*32 + dq*4];
            const __half2* ch = (const __half2*)&craw;
            float p = 0.f;
#pragma unroll
            for (int q = 0; q < 4; q++){
                float2 kv = __half22float2(kh[q]);
                float2 cs = __half22float2(ch[q]);
                float kr0 = kv.x*cs.x - kv.y*cs.y;
                float kr1 = fmaf(kv.y, cs.x, kv.x*cs.y);
                p = fmaf(qreg[2*q], kr0, p);
                p = fmaf(qreg[2*q+1], kr1, p);
            }
            p += __shfl_xor_sync(0xffffffffu, p, 1);
            p += __shfl_xor_sync(0xffffffffu, p, 2);
            p += __shfl_xor_sync(0xffffffffu, p, 4);
            if (dq == 0) in24[j][w] = p;
        }
    }
    for (int x = tid; x < 512; x += 256) s_s[x >> 3][x & 7] = be2[x & 7];
    __syncthreads();

    // edge MLP 24 -> 48 (GELU) -> 8, vectorized weights
    {
        int j = tid & 63, part = tid >> 6, hd0 = part * 12;
        float hid[12];
        {
            float4 b0 = *(const float4*)&be1[hd0];
            float4 b1 = *(const float4*)&be1[hd0+4];
            float4 b2 = *(const float4*)&be1[hd0+8];
            hid[0]=b0.x; hid[1]=b0.y; hid[2]=b0.z; hid[3]=b0.w;
            hid[4]=b1.x; hid[5]=b1.y; hid[6]=b1.z; hid[7]=b1.w;
            hid[8]=b2.x; hid[9]=b2.y; hid[10]=b2.z; hid[11]=b2.w;
        }
#pragma unroll
        for (int p = 0; p < 24; p++){
            float inp = in24[j][p];
            const float* wrow = &we1[p*48 + hd0];
            float4 w0 = *(const float4*)(wrow);
            float4 w1 = *(const float4*)(wrow+4);
            float4 w2 = *(const float4*)(wrow+8);
            hid[0]=fmaf(inp,w0.x,hid[0]); hid[1]=fmaf(inp,w0.y,hid[1]);
            hid[2]=fmaf(inp,w0.z,hid[2]); hid[3]=fmaf(inp,w0.w,hid[3]);
            hid[4]=fmaf(inp,w1.x,hid[4]); hid[5]=fmaf(inp,w1.y,hid[5]);
            hid[6]=fmaf(inp,w1.z,hid[6]); hid[7]=fmaf(inp,w1.w,hid[7]);
            hid[8]=fmaf(inp,w2.x,hid[8]); hid[9]=fmaf(inp,w2.y,hid[9]);
            hid[10]=fmaf(inp,w2.z,hid[10]); hid[11]=fmaf(inp,w2.w,hid[11]);
        }
#pragma unroll
        for (int hh = 0; hh < 12; hh++) hid[hh] = gelu_exact(hid[hh]);

        float acc[8];
#pragma unroll
        for (int h = 0; h < 8; h++) acc[h] = 0.f;
#pragma unroll
        for (int hh = 0; hh < 12; hh++){
            const float* urow = &we2[(hd0+hh)*8];
            float4 u0 = *(const float4*)(urow);
            float4 u1 = *(const float4*)(urow+4);
            float hv = hid[hh];
            acc[0]=fmaf(hv,u0.x,acc[0]); acc[1]=fmaf(hv,u0.y,acc[1]);
            acc[2]=fmaf(hv,u0.z,acc[2]); acc[3]=fmaf(hv,u0.w,acc[3]);
            acc[4]=fmaf(hv,u1.x,acc[4]); acc[5]=fmaf(hv,u1.y,acc[5]);
            acc[6]=fmaf(hv,u1.z,acc[6]); acc[7]=fmaf(hv,u1.w,acc[7]);
        }
#pragma unroll
        for (int h = 0; h < 8; h++) atomicAdd(&s_s[j][h], acc[h]);
    }
    __syncthreads();

    for (int x = tid; x < 512; x += 256){
        int jj = x >> 3, h = x & 7;
        gs_s[jj][h] = gelu_exact(s_s[jj][h]);
    }
    __syncthreads();
    for (int x = tid; x < 512; x += 256){
        int jj = x >> 3, h = x & 7;
        float cw = bc[h], gt = bg[h];
#pragma unroll
        for (int p = 0; p < 8; p++){
            cw = fmaf(gs_s[jj][p], wc[p*8 + h], cw);
            gt = fmaf(s_s[jj][p],  wg[p*8 + h], gt);
        }
        ws_s[jj][h] = cw;
        gate_s[jj][h] = fast_tanh(gt);
    }
    __syncthreads();

    // dual softmax over j per head (warp w)
    {
        float sa = s_s[l][w], sb = s_s[l+32][w];
        float m = fmaxf(sa, sb);
#pragma unroll
        for (int o = 16; o > 0; o >>= 1) m = fmaxf(m, __shfl_xor_sync(0xffffffffu, m, o));
        float ea = __expf(sa - m), eb = __expf(sb - m);
        float sum = ea + eb;
#pragma unroll
        for (int o = 16; o > 0; o >>= 1) sum += __shfl_xor_sync(0xffffffffu, sum, o);
        float inv = 1.f / sum;
        float at_a = ea * inv, at_b = eb * inv;

        float ca = ws_s[l][w], cb2 = ws_s[l+32][w];
        float m2 = fmaxf(ca, cb2);
#pragma unroll
        for (int o = 16; o > 0; o >>= 1) m2 = fmaxf(m2, __shfl_xor_sync(0xffffffffu, m2, o));
        float e2a = __expf(ca - m2), e2b = __expf(cb2 - m2);
        float sum2 = e2a + e2b;
#pragma unroll
        for (int o = 16; o > 0; o >>= 1) sum2 += __shfl_xor_sync(0xffffffffu, sum2, o);
        float inv2 = 1.f / sum2;
        __syncthreads();
        ATTN(l, w)    = at_a;
        ATTN(l+32, w) = at_b;
        ws_s[l][w]    = e2a * inv2 * gate_s[l][w];
        ws_s[l+32][w] = e2b * inv2 * gate_s[l+32][w];
    }
    __syncthreads();

    // coordinate delta
    {
        float wa = ws_s[l][w], wb = ws_s[l+32][w];
        float d0 = wa * reln[l][0] + wb * reln[l+32][0];
        float d1 = wa * reln[l][1] + wb * reln[l+32][1];
        float d2 = wa * reln[l][2] + wb * reln[l+32][2];
#pragma unroll
        for (int o = 16; o > 0; o >>= 1){
            d0 += __shfl_xor_sync(0xffffffffu, d0, o);
            d1 += __shfl_xor_sync(0xffffffffu, d1, o);
            d2 += __shfl_xor_sync(0xffffffffu, d2, o);
        }
        if (l == 0){
            float cmb = combine[w];
            atomicAdd(&delta_sm[0], d0 * cmb);
            atomicAdd(&delta_sm[1], d1 * cmb);
            atomicAdd(&delta_sm[2], d2 * cmb);
        }
    }

    // v-pass
    {
        float acc[8];
#pragma unroll
        for (int x = 0; x < 8; x++) acc[x] = 0.f;
#pragma unroll 4
        for (int t = 0; t < 16; t++){
            int j = t*4 + jg;
            float a = ATTN(j, w);
            const __half* vp = kvb + (size_t)nb_s[j] * 1024 + 512 + w*64 + dq*8;
            float4 vraw = *(const float4*)vp;
            const __half2* vh = (const __half2*)&vraw;
            float4 craw = *(const float4*)&cs_h[j*32 + dq*4];
            const __half2* ch = (const __half2*)&craw;
#pragma unroll
            for (int q = 0; q < 4; q++){
                float2 vv = __half22float2(vh[q]);
                float2 cs = __half22float2(ch[q]);
                acc[2*q]   = fmaf(a, vv.x*cs.x - vv.y*cs.y, acc[2*q]);
                acc[2*q+1] = fmaf(a, fmaf(vv.y, cs.x, vv.x*cs.y), acc[2*q+1]);
            }
        }
#pragma unroll
        for (int x = 0; x < 8; x++){
            acc[x] += __shfl_xor_sync(0xffffffffu, acc[x], 8);
            acc[x] += __shfl_xor_sync(0xffffffffu, acc[x], 16);
        }
        if (jg == 0){
            float4* po = (float4*)&g_att[(size_t)row * 512 + w*64 + dq*8];
            po[0] = make_float4(acc[0], acc[1], acc[2], acc[3]);
            po[1] = make_float4(acc[4], acc[5], acc[6], acc[7]);
        }
    }
    __syncthreads();
    if (tid < 3) out_coors[row * 3 + tid] = delta_sm[tid];
}

// ============================================================
extern "C" void kernel_launch(void* const* d_in, const int* in_sizes, int n_in,
                              void* d_out, int out_size)
{
    const float* feats   = (const float*)d_in[0];
    const float* coors   = (const float*)d_in[1];
    const float* edges   = (const float*)d_in[2];
    const float* W_qkv   = (const float*)d_in[3];
    const float* W_out   = (const float*)d_in[4];
    const float* b_out   = (const float*)d_in[5];
    const float* W_e1    = (const float*)d_in[6];
    const float* b_e1    = (const float*)d_in[7];
    const float* W_e2    = (const float*)d_in[8];
    const float* b_e2    = (const float*)d_in[9];
    const float* W_c     = (const float*)d_in[10];
    const float* b_c     = (const float*)d_in[11];
    const float* W_g     = (const float*)d_in[12];
    const float* b_g     = (const float*)d_in[13];
    const float* combine = (const float*)d_in[14];
    const float* cscale  = (const float*)d_in[15];
    float* out = (float*)d_out;

    void *p_qkv = 0, *p_att = 0, *p_kvh = 0;
    cudaGetSymbolAddress(&p_qkv, g_qkv);
    cudaGetSymbolAddress(&p_att, g_att);
    cudaGetSymbolAddress(&p_kvh, g_kvh);

    // 1) tf32 QKV GEMM, then 2-phase top-64 select
    qkv_tc_kernel<<<768, 256>>>(feats, W_qkv, (float*)p_qkv, (__half*)p_kvh);
    topk_kernel<<<4096, 256>>>(coors);

    // 2) fused attention; writes g_att and coors_delta region of d_out
    main_kernel<<<4096, 256>>>(coors, edges,
        W_e1, b_e1, W_e2, b_e2, W_c, b_c, W_g, b_g,
        combine, cscale, out + 2*2048*256);

    // 3) output projection: tf32 MMA 64x64 tiles (R14 config), bias fused
    sgemm_out_tc<<<dim3(256/64, 4096/64), 256>>>(
        (const float*)p_att, W_out, b_out, out);
}